// round 6
// baseline (speedup 1.0000x reference)
#include <cuda_runtime.h>
#include <cstddef>

#define NLAYER 8
#define DMODEL 2048
#define NHEAD 8
#define NKV 2
#define HDIM 256
#define SEQ 4096
#define FFDIM 8192
#define PLDIM 256
#define POS 2048
#define NS 2049          // valid attention positions (0..POS)
#define SSTR 2080        // padded score row stride
#define EPSF 1e-6f

// ---------------- scratch (device global, no allocation) ----------------
#define OFF_H     0
#define OFF_HN    2048
#define OFF_QKV   4096
#define OFF_Q     7168
#define OFF_KNEW  9216
#define OFF_VNEW  9728
#define OFF_ATTN  10240
#define OFF_ACT   12288
#define OFF_VEC   20480
#define OFF_G2    22528
#define OFF_SC    22784              // 8*2080 = 16640
#define OFF_PART  39424              // Wd split-4 partials (4*2048)
__device__ __align__(16) float g_scratch[39424 + 8192];

// ---------------- helpers ----------------
__device__ __forceinline__ float warp_sum(float v) {
#pragma unroll
    for (int o = 16; o; o >>= 1) v += __shfl_xor_sync(0xffffffffu, v, o);
    return v;
}
__device__ __forceinline__ float warp_max(float v) {
#pragma unroll
    for (int o = 16; o; o >>= 1) v = fmaxf(v, __shfl_xor_sync(0xffffffffu, v, o));
    return v;
}
__device__ __forceinline__ float block_sum(float v) {
    __shared__ float red[16];
    __shared__ float tot;
    int t = threadIdx.x, nw = (int)(blockDim.x >> 5);
    __syncthreads();
    v = warp_sum(v);
    if ((t & 31) == 0) red[t >> 5] = v;
    __syncthreads();
    if (t < 32) {
        float s = (t < nw) ? red[t] : 0.f;
        s = warp_sum(s);
        if (t == 0) tot = s;
    }
    __syncthreads();
    return tot;
}
__device__ __forceinline__ float block_max(float v) {
    __shared__ float red[16];
    __shared__ float tot;
    int t = threadIdx.x, nw = (int)(blockDim.x >> 5);
    __syncthreads();
    v = warp_max(v);
    if ((t & 31) == 0) red[t >> 5] = v;
    __syncthreads();
    if (t < 32) {
        float s = (t < nw) ? red[t] : -3.0e38f;
        s = warp_max(s);
        if (t == 0) tot = s;
    }
    __syncthreads();
    return tot;
}
__device__ __forceinline__ float gelu_t(float x) {
    float x3 = x * x * x;
    return 0.5f * x * (1.f + tanhf(0.7978845608028654f * (x + 0.044715f * x3)));
}
__device__ __forceinline__ float dot4(float4 a, float4 b) {
    return a.x * b.x + a.y * b.y + a.z * b.z + a.w * b.w;
}

// pipelined per-lane dot of one W row chunk (DIMC floats) against xs (smem).
// depth-2 double buffer of 4 LDG.128 — next batch in flight while current computes.
template <int DIMC>
__device__ __forceinline__ float row_dot(const float* __restrict__ Wrow,
                                         const float4* __restrict__ xs, int lane) {
    constexpr int NB = DIMC / 512;          // batches of 512 floats
    const float4* wr = (const float4*)Wrow;
    float4 cur[4];
#pragma unroll
    for (int i = 0; i < 4; i++) cur[i] = __ldcs(wr + lane + 32 * i);
    float acc = 0.f;
#pragma unroll
    for (int b = 1; b < NB; b++) {
        float4 nxt[4];
#pragma unroll
        for (int i = 0; i < 4; i++) nxt[i] = __ldcs(wr + b * 128 + lane + 32 * i);
#pragma unroll
        for (int i = 0; i < 4; i++) acc += dot4(cur[i], xs[(b - 1) * 128 + lane + 32 * i]);
#pragma unroll
        for (int i = 0; i < 4; i++) cur[i] = nxt[i];
    }
#pragma unroll
    for (int i = 0; i < 4; i++) acc += dot4(cur[i], xs[(NB - 1) * 128 + lane + 32 * i]);
    return acc;
}

// ---------------- kernels ----------------

// one-shot KV copy block (side stream): each block copies 1024 float4 of K and V,
// skipping the POS row (written exclusively by k_hnr).
// GRID MUST BE kvsz/4/1024 = 4096 blocks (float4 indexing!).
__global__ void k_copy_kv_os(const float4* __restrict__ a, const float4* __restrict__ b,
                             float4* __restrict__ oa, float4* __restrict__ ob) {
    int base = blockIdx.x * 1024 + threadIdx.x;
#pragma unroll
    for (int k = 0; k < 4; k++) {
        int j = base + k * 256;
        float4 av = __ldcs(a + j);
        float4 bv = __ldcs(b + j);
        if (((j >> 6) & (SEQ - 1)) != POS) {
            oa[j] = av;
            ob[j] = bv;
        }
    }
}

// fallback serial copy (if side stream unavailable) — still skips POS rows
__global__ void k_copy_kv_ser(const float4* __restrict__ a, const float4* __restrict__ b,
                              float4* __restrict__ oa, float4* __restrict__ ob, int n4) {
    int i = blockIdx.x * blockDim.x + threadIdx.x;
    int stride = gridDim.x * blockDim.x;
    for (; i < n4; i += stride) {
        float4 av = a[i], bv = b[i];
        if (((i >> 6) & (SEQ - 1)) != POS) { oa[i] = av; ob[i] = bv; }
    }
}

__global__ void k_copy(const float* __restrict__ src, float* __restrict__ dst, int n) {
    int i = blockIdx.x * blockDim.x + threadIdx.x;
    if (i < n) dst[i] = src[i];
}

// out = rms(x)*w   (1 block, 512 threads)
__global__ void k_rms_scale(const float* __restrict__ x, const float* __restrict__ w,
                            float* __restrict__ out) {
    int t = threadIdx.x;
    float v[4];
    float ss = 0.f;
#pragma unroll
    for (int i = 0; i < 4; i++) { v[i] = x[t + 512 * i]; ss += v[i] * v[i]; }
    ss = block_sum(ss);
    float inv = rsqrtf(ss / (float)DMODEL + EPSF);
#pragma unroll
    for (int i = 0; i < 4; i++) out[t + 512 * i] = v[i] * inv * w[t + 512 * i];
}

// h += rms(sum partials)*w
template <int NSPLIT>
__global__ void k_rms_add(const float* __restrict__ part, const float* __restrict__ w,
                          float* __restrict__ h) {
    int t = threadIdx.x;
    float v[4];
    float ss = 0.f;
#pragma unroll
    for (int i = 0; i < 4; i++) {
        int j = t + 512 * i;
        float r = 0.f;
#pragma unroll
        for (int s = 0; s < NSPLIT; s++) r += part[s * DMODEL + j];
        v[i] = r;
        ss += r * r;
    }
    ss = block_sum(ss);
    float inv = rsqrtf(ss / (float)DMODEL + EPSF);
#pragma unroll
    for (int i = 0; i < 4; i++) h[t + 512 * i] += v[i] * inv * w[t + 512 * i];
}

// h += rms(raw)*w1 ; hn = rms(h_new)*w2
__global__ void k_rms_add_norm(const float* __restrict__ raw, const float* __restrict__ w1,
                               float* __restrict__ h, const float* __restrict__ w2,
                               float* __restrict__ hn) {
    int t = threadIdx.x;
    float v[4], hv[4];
    float ss = 0.f;
#pragma unroll
    for (int i = 0; i < 4; i++) { v[i] = raw[t + 512 * i]; ss += v[i] * v[i]; }
    ss = block_sum(ss);
    float inv = rsqrtf(ss / (float)DMODEL + EPSF);
    float ss2 = 0.f;
#pragma unroll
    for (int i = 0; i < 4; i++) {
        hv[i] = h[t + 512 * i] + v[i] * inv * w1[t + 512 * i];
        ss2 += hv[i] * hv[i];
    }
    ss2 = block_sum(ss2);
    float inv2 = rsqrtf(ss2 / (float)DMODEL + EPSF);
#pragma unroll
    for (int i = 0; i < 4; i++) {
        h[t + 512 * i] = hv[i];
        hn[t + 512 * i] = hv[i] * inv2 * w2[t + 512 * i];
    }
}

// h = (h + rms(raw)*w) * sc[0] ; hn = rms(h_new)*w2
__global__ void k_rms_add_scale_norm(const float* __restrict__ raw, const float* __restrict__ w,
                                     const float* __restrict__ sc, float* __restrict__ h,
                                     const float* __restrict__ w2, float* __restrict__ hn) {
    int t = threadIdx.x;
    float v[4], hv[4];
    float ss = 0.f;
#pragma unroll
    for (int i = 0; i < 4; i++) { v[i] = raw[t + 512 * i]; ss += v[i] * v[i]; }
    ss = block_sum(ss);
    float inv = rsqrtf(ss / (float)DMODEL + EPSF);
    float s = sc[0];
    float ss2 = 0.f;
#pragma unroll
    for (int i = 0; i < 4; i++) {
        hv[i] = (h[t + 512 * i] + v[i] * inv * w[t + 512 * i]) * s;
        ss2 += hv[i] * hv[i];
    }
    ss2 = block_sum(ss2);
    float inv2 = rsqrtf(ss2 / (float)DMODEL + EPSF);
#pragma unroll
    for (int i = 0; i < 4; i++) {
        h[t + 512 * i] = hv[i];
        hn[t + 512 * i] = hv[i] * inv2 * w2[t + 512 * i];
    }
}

// fused q/k/v projection: warp-per-row, full K (2048), pipelined; grid 384
__global__ void k_qkv_stream(const float* __restrict__ Wq, const float* __restrict__ Wk,
                             const float* __restrict__ Wv, const float* __restrict__ x,
                             float* __restrict__ y) {
    __shared__ float4 xs[DMODEL / 4];
    int t = threadIdx.x, warp = t >> 5, lane = t & 31;
    xs[t] = ((const float4*)x)[t];
    xs[t + 256] = ((const float4*)x)[t + 256];
    __syncthreads();
    int row = blockIdx.x * 8 + warp;
    const float* W;
    int r;
    if (row < 2048) { W = Wq; r = row; }
    else if (row < 2560) { W = Wk; r = row - 2048; }
    else { W = Wv; r = row - 2560; }
    float acc = row_dot<DMODEL>(W + (size_t)r * DMODEL, xs, lane);
    acc = warp_sum(acc);
    if (lane == 0) y[row] = acc;
}

// generic warp-per-row GEMV (full K), pipelined; grid rows/8
template <int DIM>
__global__ void k_gemv_stream(const float* __restrict__ W, const float* __restrict__ x,
                              float* __restrict__ y) {
    __shared__ float4 xs[DIM / 4];
    int t = threadIdx.x, warp = t >> 5, lane = t & 31;
    for (int i = t; i < DIM / 4; i += 256) xs[i] = ((const float4*)x)[i];
    __syncthreads();
    int row = blockIdx.x * 8 + warp;
    float acc = row_dot<DIM>(W + (size_t)row * DIM, xs, lane);
    acc = warp_sum(acc);
    if (lane == 0) y[row] = acc;
}

// Wd split-4: grid (256 grp) x 4 chunks = 1024 blocks; pipelined per chunk (2048 floats)
__global__ void k_wd_split(const float* __restrict__ W, const float* __restrict__ x,
                           float* __restrict__ ypart) {
    constexpr int KCH = 2048;
    __shared__ float4 xs[KCH / 4];
    int t = threadIdx.x, warp = t >> 5, lane = t & 31;
    int grp = blockIdx.x & 255;
    int c = blockIdx.x >> 8;
    xs[t] = ((const float4*)(x + c * KCH))[t];
    xs[t + 256] = ((const float4*)(x + c * KCH))[t + 256];
    __syncthreads();
    int row = grp * 8 + warp;
    float acc = row_dot<KCH>(W + (size_t)row * FFDIM + c * KCH, xs, lane);
    acc = warp_sum(acc);
    if (lane == 0) ypart[c * 2048 + row] = acc;
}

// fused gate/up: warp-per-row-pair, both rows streamed back-to-back, reductions at end
__global__ void k_gateup_stream(const float* __restrict__ Wg, const float* __restrict__ Wu,
                                const float* __restrict__ x, float* __restrict__ act) {
    __shared__ float4 xs[DMODEL / 4];
    int t = threadIdx.x, warp = t >> 5, lane = t & 31;
    xs[t] = ((const float4*)x)[t];
    xs[t + 256] = ((const float4*)x)[t + 256];
    __syncthreads();
    int row = blockIdx.x * 8 + warp;
    float sg = row_dot<DMODEL>(Wg + (size_t)row * DMODEL, xs, lane);
    float su = row_dot<DMODEL>(Wu + (size_t)row * DMODEL, xs, lane);
    sg = warp_sum(sg);
    su = warp_sum(su);
    if (lane == 0) act[row] = gelu_t(sg) * su;
}

// per-layer gate: block per row (256 blocks), y[r] = gelu(W[r].h) * pl[r]
__global__ void k_plg_rowblock(const float* __restrict__ W, const float* __restrict__ x,
                               const float* __restrict__ pl, float* __restrict__ y) {
    int r = blockIdx.x, t = threadIdx.x;
    const float4* wr = (const float4*)(W + (size_t)r * DMODEL);
    const float4* xp = (const float4*)x;
    float4 a0 = __ldcs(wr + t), a1 = __ldcs(wr + t + 256);
    float s = dot4(a0, xp[t]) + dot4(a1, xp[t + 256]);
    s = block_sum(s);
    if (t == 0) y[r] = gelu_t(s) * pl[r];
}

// small gemv (plp, DIM=256): warp per row, 8 rows/block
__global__ void k_gemv256(const float* __restrict__ W, const float* __restrict__ x,
                          float* __restrict__ y) {
    __shared__ float4 xs[64];
    int t = threadIdx.x;
    if (t < 64) xs[t] = ((const float4*)x)[t];
    __syncthreads();
    int warp = t >> 5, lane = t & 31;
    int row = blockIdx.x * 8 + warp;
    const float4* wr = (const float4*)(W + (size_t)row * 256);
    float s = dot4(__ldcs(wr + lane), xs[lane]) + dot4(__ldcs(wr + lane + 32), xs[lane + 32]);
    s = warp_sum(s);
    if (lane == 0) y[row] = s;
}

// per-head rms norm + (qn/kn) scale + rope
__global__ void k_hnr(const float* __restrict__ qkv, const float* __restrict__ qn,
                      const float* __restrict__ kn, const float* __restrict__ cosp,
                      const float* __restrict__ sinp, float* __restrict__ q,
                      float* __restrict__ knew, float* __restrict__ vnew,
                      float* __restrict__ outK_l, float* __restrict__ outV_l) {
    int b = blockIdx.x, t = threadIdx.x;
    float x = qkv[b * 256 + t];
    float ss = block_sum(x * x);
    float inv = rsqrtf(ss / (float)HDIM + EPSF);
    __shared__ float sv[256];
    float val;
    if (b < 8) val = x * inv * qn[t];
    else if (b < 10) val = x * inv * kn[t];
    else val = x * inv;
    sv[t] = val;
    __syncthreads();
    float out;
    if (b < 10) {
        float other = (t < 128) ? -sv[t + 128] : sv[t - 128];
        out = val * cosp[t] + other * sinp[t];
    } else {
        out = val;
    }
    if (b < 8) {
        q[b * 256 + t] = out;
    } else if (b < 10) {
        int kv = b - 8;
        knew[kv * 256 + t] = out;
        outK_l[((size_t)kv * SEQ + POS) * HDIM + t] = out;
    } else {
        int kv = b - 10;
        vnew[kv * 256 + t] = out;
        outV_l[((size_t)kv * SEQ + POS) * HDIM + t] = out;
    }
}

// attention scores: grid (8 heads, 33 chunks of 64), 256 threads (8 warps)
__global__ void k_scores(const float* __restrict__ q, const float* __restrict__ Kl,
                         const float* __restrict__ knew, float* __restrict__ scores) {
    int h = blockIdx.x, c = blockIdx.y, t = threadIdx.x;
    int kv = h >> 2;
    __shared__ float4 qs[64];
    if (t < 64) qs[t] = ((const float4*)(q + h * 256))[t];
    __syncthreads();
    int warp = t >> 5, lane = t & 31;
    const float* Kbase = Kl + (size_t)kv * SEQ * HDIM;
    const float* knv = knew + kv * HDIM;
    int s0 = c * 64;
#pragma unroll
    for (int i = 0; i < 8; i++) {
        int s = s0 + i * 8 + warp;
        if (s <= POS) {
            const float4* kr = (s == POS) ? (const float4*)knv
                                          : (const float4*)(Kbase + (size_t)s * HDIM);
            float4 a0 = __ldcs(kr + lane), a1 = __ldcs(kr + lane + 32);
            float acc = dot4(a0, qs[lane]) + dot4(a1, qs[lane + 32]);
            acc = warp_sum(acc);
            if (lane == 0) scores[h * SSTR + s] = acc;
        }
    }
}

// softmax per head over NS positions; also zeroes attn accumulator
__global__ void k_softmax(float* __restrict__ scores, float* __restrict__ attn) {
    int h = blockIdx.x, t = threadIdx.x;
    __shared__ float sh[NS];
    float m = -3.0e38f;
    for (int s = t; s < NS; s += 256) {
        float v = scores[h * SSTR + s];
        sh[s] = v;
        m = fmaxf(m, v);
    }
    m = block_max(m);
    float sum = 0.f;
    for (int s = t; s < NS; s += 256) {
        float e = __expf(sh[s] - m);
        sh[s] = e;
        sum += e;
    }
    sum = block_sum(sum);
    float invz = 1.f / sum;
    for (int s = t; s < NS; s += 256) scores[h * SSTR + s] = sh[s] * invz;
    attn[h * HDIM + t] = 0.f;
}

// attn[h,d] += sum over chunk of p[s]*V[s,d]; grid (8, 33), 256 threads (= d)
__global__ void k_attnv(const float* __restrict__ scores, const float* __restrict__ Vl,
                        const float* __restrict__ vnew, float* __restrict__ attn) {
    int h = blockIdx.x, c = blockIdx.y, t = threadIdx.x;
    int kv = h >> 2;
    __shared__ float ps[64];
    int s0 = c * 64;
    if (t < 64) {
        int s = s0 + t;
        ps[t] = (s <= POS) ? scores[h * SSTR + s] : 0.f;
    }
    __syncthreads();
    const float* Vbase = Vl + (size_t)kv * SEQ * HDIM;
    const float* vnv = vnew + kv * HDIM;
    float acc = 0.f;
#pragma unroll 4
    for (int i = 0; i < 64; i++) {
        int s = s0 + i;
        const float* vr = (s == POS) ? vnv : (Vbase + (size_t)s * HDIM);
        acc += ps[i] * vr[t];
    }
    atomicAdd(&attn[h * HDIM + t], acc);
}

// ---------------- host launcher ----------------
extern "C" void kernel_launch(void* const* d_in, const int* in_sizes, int n_in,
                              void* d_out, int out_size) {
    const float* hs    = (const float*)d_in[0];
    const float* pls   = (const float*)d_in[3];
    const float* cos_s = (const float*)d_in[4];
    const float* sin_s = (const float*)d_in[5];
    const float* cos_f = (const float*)d_in[6];
    const float* sin_f = (const float*)d_in[7];
    const float* K_in  = (const float*)d_in[8];
    const float* V_in  = (const float*)d_in[9];
    const float* Wq    = (const float*)d_in[10];
    const float* Wk    = (const float*)d_in[11];
    const float* Wv    = (const float*)d_in[12];
    const float* Wo    = (const float*)d_in[13];
    const float* qn    = (const float*)d_in[14];
    const float* kn    = (const float*)d_in[15];
    const float* ln_in   = (const float*)d_in[16];
    const float* ln_pa   = (const float*)d_in[17];
    const float* ln_pre  = (const float*)d_in[18];
    const float* ln_post = (const float*)d_in[19];
    const float* ln_pl   = (const float*)d_in[20];
    const float* Wg    = (const float*)d_in[21];
    const float* Wu    = (const float*)d_in[22];
    const float* Wd    = (const float*)d_in[23];
    const float* Wplg  = (const float*)d_in[24];
    const float* Wplp  = (const float*)d_in[25];
    const float* lsc   = (const float*)d_in[26];

    float* out = (float*)d_out;
    const size_t kvsz = (size_t)NLAYER * NKV * SEQ * HDIM;  // 16,777,216 floats
    float* outK = out + DMODEL;
    float* outV = outK + kvsz;

    float* sb = nullptr;
    cudaGetSymbolAddress((void**)&sb, g_scratch);
    float* b_h    = sb + OFF_H;
    float* b_hn   = sb + OFF_HN;
    float* b_qkv  = sb + OFF_QKV;
    float* b_q    = sb + OFF_Q;
    float* b_knew = sb + OFF_KNEW;
    float* b_vnew = sb + OFF_VNEW;
    float* b_attn = sb + OFF_ATTN;
    float* b_act  = sb + OFF_ACT;
    float* b_vec  = sb + OFF_VEC;
    float* b_g2   = sb + OFF_G2;
    float* b_sc   = sb + OFF_SC;
    float* b_part = sb + OFF_PART;

    // side stream (low priority) + events, created once
    static cudaStream_t s2 = nullptr;
    static cudaEvent_t evF = nullptr, evJ = nullptr;
    static bool side_ok = false;
    if (!s2) {
        int lo = 0, hi = 0;
        cudaDeviceGetStreamPriorityRange(&lo, &hi);
        side_ok = (cudaStreamCreateWithPriority(&s2, cudaStreamNonBlocking, lo) == cudaSuccess) &&
                  (cudaEventCreateWithFlags(&evF, cudaEventDisableTiming) == cudaSuccess) &&
                  (cudaEventCreateWithFlags(&evJ, cudaEventDisableTiming) == cudaSuccess);
    }

    // KV cache copy (skips POS rows — those are written exclusively by k_hnr).
    // n4 = kvsz/4 = 4,194,304 float4 per array; 4096 blocks * 1024 float4 = exact.
    if (side_ok) {
        cudaEventRecord(evF, 0);
        cudaStreamWaitEvent(s2, evF, 0);
        k_copy_kv_os<<<4096, 256, 0, s2>>>((const float4*)K_in, (const float4*)V_in,
                                           (float4*)outK, (float4*)outV);
        cudaEventRecord(evJ, s2);
    } else {
        k_copy_kv_ser<<<1184, 256>>>((const float4*)K_in, (const float4*)V_in,
                                     (float4*)outK, (float4*)outV, (int)(kvsz / 4));
    }

    // h = hidden_states ; hn = rms(h)*ln_in[0]
    k_copy<<<8, 256>>>(hs, b_h, DMODEL);
    k_rms_scale<<<1, 512>>>(b_h, ln_in, b_hn);

    for (int l = 0; l < NLAYER; l++) {
        const float* Wq_l = Wq + (size_t)l * 2048 * 2048;
        const float* Wk_l = Wk + (size_t)l * 512 * 2048;
        const float* Wv_l = Wv + (size_t)l * 512 * 2048;
        const float* Wo_l = Wo + (size_t)l * 2048 * 2048;
        const float* Wg_l = Wg + (size_t)l * 8192 * 2048;
        const float* Wu_l = Wu + (size_t)l * 8192 * 2048;
        const float* Wd_l = Wd + (size_t)l * 2048 * 8192;
        const float* Wplg_l = Wplg + (size_t)l * 256 * 2048;
        const float* Wplp_l = Wplp + (size_t)l * 2048 * 256;
        const float* K_l = K_in + (size_t)l * NKV * SEQ * HDIM;
        const float* V_l = V_in + (size_t)l * NKV * SEQ * HDIM;
        float* outK_l = outK + (size_t)l * NKV * SEQ * HDIM;
        float* outV_l = outV + (size_t)l * NKV * SEQ * HDIM;
        bool full = ((l + 1) % 5) == 0;
        const float* cp = full ? cos_f : cos_s;
        const float* sp = full ? sin_f : sin_s;
        const float* ln_in_next = ln_in + ((l + 1 < NLAYER) ? (l + 1) : 0) * DMODEL;

        // attention block
        k_qkv_stream<<<384, 256>>>(Wq_l, Wk_l, Wv_l, b_hn, b_qkv);
        k_hnr<<<12, 256>>>(b_qkv, qn + l * HDIM, kn + l * HDIM, cp, sp,
                           b_q, b_knew, b_vnew, outK_l, outV_l);
        k_scores<<<dim3(8, 33), 256>>>(b_q, K_l, b_knew, b_sc);
        k_softmax<<<8, 256>>>(b_sc, b_attn);
        k_attnv<<<dim3(8, 33), 256>>>(b_sc, V_l, b_vnew, b_attn);
        k_gemv_stream<2048><<<256, 256>>>(Wo_l, b_attn, b_vec);
        k_rms_add_norm<<<1, 512>>>(b_vec, ln_pa + l * DMODEL, b_h,
                                   ln_pre + l * DMODEL, b_hn);
        // MLP block
        k_gateup_stream<<<1024, 256>>>(Wg_l, Wu_l, b_hn, b_act);
        k_wd_split<<<1024, 256>>>(Wd_l, b_act, b_part);
        k_rms_add<4><<<1, 512>>>(b_part, ln_post + l * DMODEL, b_h);
        // per-layer block
        k_plg_rowblock<<<256, 256>>>(Wplg_l, b_h, pls + l * PLDIM, b_g2);
        k_gemv256<<<256, 256>>>(Wplp_l, b_g2, b_vec);
        k_rms_add_scale_norm<<<1, 512>>>(b_vec, ln_pl + l * DMODEL, lsc + l,
                                         b_h, ln_in_next, b_hn);
    }

    // join side stream, then final hidden state
    if (side_ok) cudaStreamWaitEvent(0, evJ, 0);
    k_copy<<<8, 256>>>(b_h, out, DMODEL);
}

// round 7
// speedup vs baseline: 1.0341x; 1.0341x over previous
#include <cuda_runtime.h>
#include <cstddef>
#include <cstdint>

#define NLAYER 8
#define DMODEL 2048
#define NHEAD 8
#define NKV 2
#define HDIM 256
#define SEQ 4096
#define FFDIM 8192
#define PLDIM 256
#define POS 2048
#define NS 2049          // valid attention positions (0..POS)
#define SSTR 2080        // padded score row stride
#define EPSF 1e-6f

// dynamic smem layout for cp.async GEMV kernels (in float4):
//   xs:  [0, 512)        x chunk (2048 floats)
//   ws:  [512, 512+3072) 3 stages x 8 warps x 128 float4
//   red: 8 floats after
#define XS4   512
#define WS4   3072
#define SS4   1024              // float4 per stage (8 warps * 128)
#define SMEMB ((XS4 + WS4) * 16 + 64)

// ---------------- scratch (device global, no allocation) ----------------
#define OFF_H     0
#define OFF_HN    2048
#define OFF_QKV   4096
#define OFF_Q     7168
#define OFF_KNEW  9216
#define OFF_VNEW  9728
#define OFF_ATTN  10240
#define OFF_ACT   12288
#define OFF_VEC   20480
#define OFF_G2    22528
#define OFF_SC    22784              // 8*2080 = 16640
#define OFF_PART  39424              // Wd split-4 partials (4*2048)
__device__ __align__(16) float g_scratch[39424 + 8192];

// ---------------- helpers ----------------
__device__ __forceinline__ float warp_sum(float v) {
#pragma unroll
    for (int o = 16; o; o >>= 1) v += __shfl_xor_sync(0xffffffffu, v, o);
    return v;
}
__device__ __forceinline__ float warp_max(float v) {
#pragma unroll
    for (int o = 16; o; o >>= 1) v = fmaxf(v, __shfl_xor_sync(0xffffffffu, v, o));
    return v;
}
__device__ __forceinline__ float block_sum(float v) {
    __shared__ float red[16];
    __shared__ float tot;
    int t = threadIdx.x, nw = (int)(blockDim.x >> 5);
    __syncthreads();
    v = warp_sum(v);
    if ((t & 31) == 0) red[t >> 5] = v;
    __syncthreads();
    if (t < 32) {
        float s = (t < nw) ? red[t] : 0.f;
        s = warp_sum(s);
        if (t == 0) tot = s;
    }
    __syncthreads();
    return tot;
}
__device__ __forceinline__ float block_max(float v) {
    __shared__ float red[16];
    __shared__ float tot;
    int t = threadIdx.x, nw = (int)(blockDim.x >> 5);
    __syncthreads();
    v = warp_max(v);
    if ((t & 31) == 0) red[t >> 5] = v;
    __syncthreads();
    if (t < 32) {
        float s = (t < nw) ? red[t] : -3.0e38f;
        s = warp_max(s);
        if (t == 0) tot = s;
    }
    __syncthreads();
    return tot;
}
__device__ __forceinline__ float gelu_t(float x) {
    float x3 = x * x * x;
    return 0.5f * x * (1.f + tanhf(0.7978845608028654f * (x + 0.044715f * x3)));
}
__device__ __forceinline__ float dot4(float4 a, float4 b) {
    return a.x * b.x + a.y * b.y + a.z * b.z + a.w * b.w;
}

// ---------------- cp.async machinery ----------------
__device__ __forceinline__ void cp16(float4* sptr, const float4* gptr) {
    uint32_t sa = (uint32_t)__cvta_generic_to_shared(sptr);
    asm volatile("cp.async.cg.shared.global [%0], [%1], 16;\n" :: "r"(sa), "l"(gptr) : "memory");
}
__device__ __forceinline__ void cp_commit() {
    asm volatile("cp.async.commit_group;\n" ::: "memory");
}
// issue one 512-float stage of this warp's row (4 cp.async of 16B per lane) + commit
__device__ __forceinline__ void rs_issue(const float4* gp, float4* wstage, int lane) {
#pragma unroll
    for (int i = 0; i < 4; i++) cp16(wstage + lane + 32 * i, gp + lane + 32 * i);
    cp_commit();
}
// prologue: issue first min(3,NST) stages
template <int NST>
__device__ __forceinline__ void rs_prologue(const float4* gp, float4* wswarp, int lane) {
#pragma unroll
    for (int s = 0; s < (NST < 3 ? NST : 3); s++)
        rs_issue(gp + s * 128, wswarp + s * SS4, lane);
}
// steady loop: wait oldest, consume from smem ring, issue next. Per-warp only —
// each lane consumes exactly the addresses it issued, so no block barrier needed.
template <int NST>
__device__ __forceinline__ float rs_loop(const float4* gp, float4* wswarp,
                                         const float4* xsw, int lane) {
    float acc = 0.f;
#pragma unroll
    for (int s = 0; s < NST; s++) {
        int rem = NST - 1 - s;
        if (rem >= 2)      asm volatile("cp.async.wait_group 2;\n" ::: "memory");
        else if (rem == 1) asm volatile("cp.async.wait_group 1;\n" ::: "memory");
        else               asm volatile("cp.async.wait_group 0;\n" ::: "memory");
        const float4* wstage = wswarp + (s % 3) * SS4;
#pragma unroll
        for (int i = 0; i < 4; i++)
            acc += dot4(wstage[lane + 32 * i], xsw[s * 128 + lane + 32 * i]);
        if (s + 3 < NST)
            rs_issue(gp + (s + 3) * 128, wswarp + ((s + 3) % 3) * SS4, lane);
    }
    return acc;
}

// ---------------- kernels ----------------

// one-shot KV copy block (side stream): each block copies 1024 float4 of K and V,
// skipping the POS row (written exclusively by k_hnr). GRID = 4096 (float4 indexing).
__global__ void k_copy_kv_os(const float4* __restrict__ a, const float4* __restrict__ b,
                             float4* __restrict__ oa, float4* __restrict__ ob) {
    int base = blockIdx.x * 1024 + threadIdx.x;
#pragma unroll
    for (int k = 0; k < 4; k++) {
        int j = base + k * 256;
        float4 av = __ldcs(a + j);
        float4 bv = __ldcs(b + j);
        if (((j >> 6) & (SEQ - 1)) != POS) {
            oa[j] = av;
            ob[j] = bv;
        }
    }
}
// fallback serial copy — still skips POS rows
__global__ void k_copy_kv_ser(const float4* __restrict__ a, const float4* __restrict__ b,
                              float4* __restrict__ oa, float4* __restrict__ ob, int n4) {
    int i = blockIdx.x * blockDim.x + threadIdx.x;
    int stride = gridDim.x * blockDim.x;
    for (; i < n4; i += stride) {
        float4 av = a[i], bv = b[i];
        if (((i >> 6) & (SEQ - 1)) != POS) { oa[i] = av; ob[i] = bv; }
    }
}

__global__ void k_copy(const float* __restrict__ src, float* __restrict__ dst, int n) {
    int i = blockIdx.x * blockDim.x + threadIdx.x;
    if (i < n) dst[i] = src[i];
}

// h = hs ; hn = rms(hs)*w   (1 block, 512 threads)
__global__ void k_rms_init(const float* __restrict__ hs, const float* __restrict__ w,
                           float* __restrict__ h, float* __restrict__ hn) {
    int t = threadIdx.x;
    float v[4];
    float ss = 0.f;
#pragma unroll
    for (int i = 0; i < 4; i++) { v[i] = hs[t + 512 * i]; ss += v[i] * v[i]; }
    ss = block_sum(ss);
    float inv = rsqrtf(ss / (float)DMODEL + EPSF);
#pragma unroll
    for (int i = 0; i < 4; i++) {
        h[t + 512 * i] = v[i];
        hn[t + 512 * i] = v[i] * inv * w[t + 512 * i];
    }
}

// h += rms(sum partials)*w
template <int NSPLIT>
__global__ void k_rms_add(const float* __restrict__ part, const float* __restrict__ w,
                          float* __restrict__ h) {
    int t = threadIdx.x;
    float v[4];
    float ss = 0.f;
#pragma unroll
    for (int i = 0; i < 4; i++) {
        int j = t + 512 * i;
        float r = 0.f;
#pragma unroll
        for (int s = 0; s < NSPLIT; s++) r += part[s * DMODEL + j];
        v[i] = r;
        ss += r * r;
    }
    ss = block_sum(ss);
    float inv = rsqrtf(ss / (float)DMODEL + EPSF);
#pragma unroll
    for (int i = 0; i < 4; i++) h[t + 512 * i] += v[i] * inv * w[t + 512 * i];
}

// h += rms(raw)*w1 ; hn = rms(h_new)*w2
__global__ void k_rms_add_norm(const float* __restrict__ raw, const float* __restrict__ w1,
                               float* __restrict__ h, const float* __restrict__ w2,
                               float* __restrict__ hn) {
    int t = threadIdx.x;
    float v[4], hv[4];
    float ss = 0.f;
#pragma unroll
    for (int i = 0; i < 4; i++) { v[i] = raw[t + 512 * i]; ss += v[i] * v[i]; }
    ss = block_sum(ss);
    float inv = rsqrtf(ss / (float)DMODEL + EPSF);
    float ss2 = 0.f;
#pragma unroll
    for (int i = 0; i < 4; i++) {
        hv[i] = h[t + 512 * i] + v[i] * inv * w1[t + 512 * i];
        ss2 += hv[i] * hv[i];
    }
    ss2 = block_sum(ss2);
    float inv2 = rsqrtf(ss2 / (float)DMODEL + EPSF);
#pragma unroll
    for (int i = 0; i < 4; i++) {
        h[t + 512 * i] = hv[i];
        hn[t + 512 * i] = hv[i] * inv2 * w2[t + 512 * i];
    }
}

// h = (h + rms(raw)*w) * sc[0] ; hn = rms(h_new)*w2
__global__ void k_rms_add_scale_norm(const float* __restrict__ raw, const float* __restrict__ w,
                                     const float* __restrict__ sc, float* __restrict__ h,
                                     const float* __restrict__ w2, float* __restrict__ hn) {
    int t = threadIdx.x;
    float v[4], hv[4];
    float ss = 0.f;
#pragma unroll
    for (int i = 0; i < 4; i++) { v[i] = raw[t + 512 * i]; ss += v[i] * v[i]; }
    ss = block_sum(ss);
    float inv = rsqrtf(ss / (float)DMODEL + EPSF);
    float s = sc[0];
    float ss2 = 0.f;
#pragma unroll
    for (int i = 0; i < 4; i++) {
        hv[i] = (h[t + 512 * i] + v[i] * inv * w[t + 512 * i]) * s;
        ss2 += hv[i] * hv[i];
    }
    ss2 = block_sum(ss2);
    float inv2 = rsqrtf(ss2 / (float)DMODEL + EPSF);
#pragma unroll
    for (int i = 0; i < 4; i++) {
        h[t + 512 * i] = hv[i];
        hn[t + 512 * i] = hv[i] * inv2 * w2[t + 512 * i];
    }
}

// fused q/k/v projection, cp.async multistage: grid 384, warp per row, NST=4
__global__ void k_qkv_cp(const float* __restrict__ Wq, const float* __restrict__ Wk,
                         const float* __restrict__ Wv, const float* __restrict__ x,
                         float* __restrict__ y) {
    extern __shared__ float4 sm[];
    float4* xs = sm;
    float4* ws = sm + XS4;
    int t = threadIdx.x, warp = t >> 5, lane = t & 31;
    int row = blockIdx.x * 8 + warp;
    const float* W;
    int r;
    if (row < 2048) { W = Wq; r = row; }
    else if (row < 2560) { W = Wk; r = row - 2048; }
    else { W = Wv; r = row - 2560; }
    const float4* gp = (const float4*)(W + (size_t)r * DMODEL);
    float4* wswarp = ws + warp * 128;
    rs_prologue<4>(gp, wswarp, lane);
    xs[t] = ((const float4*)x)[t];
    xs[t + 256] = ((const float4*)x)[t + 256];
    __syncthreads();
    float acc = rs_loop<4>(gp, wswarp, xs, lane);
    acc = warp_sum(acc);
    if (lane == 0) y[row] = acc;
}

// generic full-K (2048) GEMV: grid rows/8 (Wo: 256)
__global__ void k_gemv_cp(const float* __restrict__ W, const float* __restrict__ x,
                          float* __restrict__ y) {
    extern __shared__ float4 sm[];
    float4* xs = sm;
    float4* ws = sm + XS4;
    int t = threadIdx.x, warp = t >> 5, lane = t & 31;
    int row = blockIdx.x * 8 + warp;
    const float4* gp = (const float4*)(W + (size_t)row * DMODEL);
    float4* wswarp = ws + warp * 128;
    rs_prologue<4>(gp, wswarp, lane);
    xs[t] = ((const float4*)x)[t];
    xs[t + 256] = ((const float4*)x)[t + 256];
    __syncthreads();
    float acc = rs_loop<4>(gp, wswarp, xs, lane);
    acc = warp_sum(acc);
    if (lane == 0) y[row] = acc;
}

// fused gate/up: grid 2048, block = 4 output rows. warps 0-3 stream Wg rows,
// warps 4-7 stream Wu rows; combine via smem.
__global__ void k_gateup_cp(const float* __restrict__ Wg, const float* __restrict__ Wu,
                            const float* __restrict__ x, float* __restrict__ act) {
    extern __shared__ float4 sm[];
    float4* xs = sm;
    float4* ws = sm + XS4;
    float* red = (float*)(sm + XS4 + WS4);
    int t = threadIdx.x, warp = t >> 5, lane = t & 31;
    int row = blockIdx.x * 4 + (warp & 3);
    const float* W = (warp < 4) ? Wg : Wu;
    const float4* gp = (const float4*)(W + (size_t)row * DMODEL);
    float4* wswarp = ws + warp * 128;
    rs_prologue<4>(gp, wswarp, lane);
    xs[t] = ((const float4*)x)[t];
    xs[t + 256] = ((const float4*)x)[t + 256];
    __syncthreads();
    float acc = rs_loop<4>(gp, wswarp, xs, lane);
    acc = warp_sum(acc);
    if (lane == 0) red[warp] = acc;
    __syncthreads();
    if (t < 4) act[blockIdx.x * 4 + t] = gelu_t(red[t]) * red[t + 4];
}

// Wd split-4: grid 1024 (grp 0..255 | chunk 0..3), warp per row-chunk (2048 floats)
__global__ void k_wd_cp(const float* __restrict__ W, const float* __restrict__ x,
                        float* __restrict__ ypart) {
    extern __shared__ float4 sm[];
    float4* xs = sm;
    float4* ws = sm + XS4;
    int t = threadIdx.x, warp = t >> 5, lane = t & 31;
    int grp = blockIdx.x & 255;
    int c = blockIdx.x >> 8;
    int row = grp * 8 + warp;
    const float4* gp = (const float4*)(W + (size_t)row * FFDIM + c * 2048);
    float4* wswarp = ws + warp * 128;
    rs_prologue<4>(gp, wswarp, lane);
    const float4* xp = (const float4*)(x + c * 2048);
    xs[t] = xp[t];
    xs[t + 256] = xp[t + 256];
    __syncthreads();
    float acc = rs_loop<4>(gp, wswarp, xs, lane);
    acc = warp_sum(acc);
    if (lane == 0) ypart[c * 2048 + row] = acc;
}

// per-layer gate: block per row (256 blocks), y[r] = gelu(W[r].h) * pl[r]
__global__ void k_plg_rowblock(const float* __restrict__ W, const float* __restrict__ x,
                               const float* __restrict__ pl, float* __restrict__ y) {
    int r = blockIdx.x, t = threadIdx.x;
    const float4* wr = (const float4*)(W + (size_t)r * DMODEL);
    const float4* xp = (const float4*)x;
    float4 a0 = __ldcs(wr + t), a1 = __ldcs(wr + t + 256);
    float s = dot4(a0, xp[t]) + dot4(a1, xp[t + 256]);
    s = block_sum(s);
    if (t == 0) y[r] = gelu_t(s) * pl[r];
}

// small gemv (plp, DIM=256): warp per row, 8 rows/block
__global__ void k_gemv256(const float* __restrict__ W, const float* __restrict__ x,
                          float* __restrict__ y) {
    __shared__ float4 xs[64];
    int t = threadIdx.x;
    if (t < 64) xs[t] = ((const float4*)x)[t];
    __syncthreads();
    int warp = t >> 5, lane = t & 31;
    int row = blockIdx.x * 8 + warp;
    const float4* wr = (const float4*)(W + (size_t)row * 256);
    float s = dot4(__ldcs(wr + lane), xs[lane]) + dot4(__ldcs(wr + lane + 32), xs[lane + 32]);
    s = warp_sum(s);
    if (lane == 0) y[row] = s;
}

// per-head rms norm + (qn/kn) scale + rope
__global__ void k_hnr(const float* __restrict__ qkv, const float* __restrict__ qn,
                      const float* __restrict__ kn, const float* __restrict__ cosp,
                      const float* __restrict__ sinp, float* __restrict__ q,
                      float* __restrict__ knew, float* __restrict__ vnew,
                      float* __restrict__ outK_l, float* __restrict__ outV_l) {
    int b = blockIdx.x, t = threadIdx.x;
    float x = qkv[b * 256 + t];
    float ss = block_sum(x * x);
    float inv = rsqrtf(ss / (float)HDIM + EPSF);
    __shared__ float sv[256];
    float val;
    if (b < 8) val = x * inv * qn[t];
    else if (b < 10) val = x * inv * kn[t];
    else val = x * inv;
    sv[t] = val;
    __syncthreads();
    float out;
    if (b < 10) {
        float other = (t < 128) ? -sv[t + 128] : sv[t - 128];
        out = val * cosp[t] + other * sinp[t];
    } else {
        out = val;
    }
    if (b < 8) {
        q[b * 256 + t] = out;
    } else if (b < 10) {
        int kv = b - 8;
        knew[kv * 256 + t] = out;
        outK_l[((size_t)kv * SEQ + POS) * HDIM + t] = out;
    } else {
        int kv = b - 10;
        vnew[kv * 256 + t] = out;
        outV_l[((size_t)kv * SEQ + POS) * HDIM + t] = out;
    }
}

// attention scores: grid (8 heads, 33 chunks of 64), 256 threads (8 warps)
__global__ void k_scores(const float* __restrict__ q, const float* __restrict__ Kl,
                         const float* __restrict__ knew, float* __restrict__ scores) {
    int h = blockIdx.x, c = blockIdx.y, t = threadIdx.x;
    int kv = h >> 2;
    __shared__ float4 qs[64];
    if (t < 64) qs[t] = ((const float4*)(q + h * 256))[t];
    __syncthreads();
    int warp = t >> 5, lane = t & 31;
    const float* Kbase = Kl + (size_t)kv * SEQ * HDIM;
    const float* knv = knew + kv * HDIM;
    int s0 = c * 64;
#pragma unroll
    for (int i = 0; i < 8; i++) {
        int s = s0 + i * 8 + warp;
        if (s <= POS) {
            const float4* kr = (s == POS) ? (const float4*)knv
                                          : (const float4*)(Kbase + (size_t)s * HDIM);
            float4 a0 = __ldcs(kr + lane), a1 = __ldcs(kr + lane + 32);
            float acc = dot4(a0, qs[lane]) + dot4(a1, qs[lane + 32]);
            acc = warp_sum(acc);
            if (lane == 0) scores[h * SSTR + s] = acc;
        }
    }
}

// softmax per head over NS positions; also zeroes attn accumulator
__global__ void k_softmax(float* __restrict__ scores, float* __restrict__ attn) {
    int h = blockIdx.x, t = threadIdx.x;
    __shared__ float sh[NS];
    float m = -3.0e38f;
    for (int s = t; s < NS; s += 256) {
        float v = scores[h * SSTR + s];
        sh[s] = v;
        m = fmaxf(m, v);
    }
    m = block_max(m);
    float sum = 0.f;
    for (int s = t; s < NS; s += 256) {
        float e = __expf(sh[s] - m);
        sh[s] = e;
        sum += e;
    }
    sum = block_sum(sum);
    float invz = 1.f / sum;
    for (int s = t; s < NS; s += 256) scores[h * SSTR + s] = sh[s] * invz;
    attn[h * HDIM + t] = 0.f;
}

// attn[h,d] += sum over chunk of p[s]*V[s,d]; grid (8, 33), 256 threads (= d)
__global__ void k_attnv(const float* __restrict__ scores, const float* __restrict__ Vl,
                        const float* __restrict__ vnew, float* __restrict__ attn) {
    int h = blockIdx.x, c = blockIdx.y, t = threadIdx.x;
    int kv = h >> 2;
    __shared__ float ps[64];
    int s0 = c * 64;
    if (t < 64) {
        int s = s0 + t;
        ps[t] = (s <= POS) ? scores[h * SSTR + s] : 0.f;
    }
    __syncthreads();
    const float* Vbase = Vl + (size_t)kv * SEQ * HDIM;
    const float* vnv = vnew + kv * HDIM;
    float acc = 0.f;
#pragma unroll 4
    for (int i = 0; i < 64; i++) {
        int s = s0 + i;
        const float* vr = (s == POS) ? vnv : (Vbase + (size_t)s * HDIM);
        acc += ps[i] * vr[t];
    }
    atomicAdd(&attn[h * HDIM + t], acc);
}

// ---------------- host launcher ----------------
extern "C" void kernel_launch(void* const* d_in, const int* in_sizes, int n_in,
                              void* d_out, int out_size) {
    const float* hs    = (const float*)d_in[0];
    const float* pls   = (const float*)d_in[3];
    const float* cos_s = (const float*)d_in[4];
    const float* sin_s = (const float*)d_in[5];
    const float* cos_f = (const float*)d_in[6];
    const float* sin_f = (const float*)d_in[7];
    const float* K_in  = (const float*)d_in[8];
    const float* V_in  = (const float*)d_in[9];
    const float* Wq    = (const float*)d_in[10];
    const float* Wk    = (const float*)d_in[11];
    const float* Wv    = (const float*)d_in[12];
    const float* Wo    = (const float*)d_in[13];
    const float* qn    = (const float*)d_in[14];
    const float* kn    = (const float*)d_in[15];
    const float* ln_in   = (const float*)d_in[16];
    const float* ln_pa   = (const float*)d_in[17];
    const float* ln_pre  = (const float*)d_in[18];
    const float* ln_post = (const float*)d_in[19];
    const float* ln_pl   = (const float*)d_in[20];
    const float* Wg    = (const float*)d_in[21];
    const float* Wu    = (const float*)d_in[22];
    const float* Wd    = (const float*)d_in[23];
    const float* Wplg  = (const float*)d_in[24];
    const float* Wplp  = (const float*)d_in[25];
    const float* lsc   = (const float*)d_in[26];

    float* out = (float*)d_out;
    const size_t kvsz = (size_t)NLAYER * NKV * SEQ * HDIM;  // 16,777,216 floats
    float* outK = out + DMODEL;
    float* outV = outK + kvsz;

    float* sb = nullptr;
    cudaGetSymbolAddress((void**)&sb, g_scratch);
    float* b_h    = sb + OFF_H;
    float* b_hn   = sb + OFF_HN;
    float* b_qkv  = sb + OFF_QKV;
    float* b_q    = sb + OFF_Q;
    float* b_knew = sb + OFF_KNEW;
    float* b_vnew = sb + OFF_VNEW;
    float* b_attn = sb + OFF_ATTN;
    float* b_act  = sb + OFF_ACT;
    float* b_vec  = sb + OFF_VEC;
    float* b_g2   = sb + OFF_G2;
    float* b_sc   = sb + OFF_SC;
    float* b_part = sb + OFF_PART;

    // one-time setup: smem opt-in + side stream/events
    static bool attrs_done = false;
    if (!attrs_done) {
        cudaFuncSetAttribute(k_qkv_cp, cudaFuncAttributeMaxDynamicSharedMemorySize, SMEMB);
        cudaFuncSetAttribute(k_gemv_cp, cudaFuncAttributeMaxDynamicSharedMemorySize, SMEMB);
        cudaFuncSetAttribute(k_gateup_cp, cudaFuncAttributeMaxDynamicSharedMemorySize, SMEMB);
        cudaFuncSetAttribute(k_wd_cp, cudaFuncAttributeMaxDynamicSharedMemorySize, SMEMB);
        attrs_done = true;
    }
    static cudaStream_t s2 = nullptr;
    static cudaEvent_t evF = nullptr, evJ = nullptr;
    static bool side_ok = false;
    if (!s2) {
        int lo = 0, hi = 0;
        cudaDeviceGetStreamPriorityRange(&lo, &hi);
        side_ok = (cudaStreamCreateWithPriority(&s2, cudaStreamNonBlocking, lo) == cudaSuccess) &&
                  (cudaEventCreateWithFlags(&evF, cudaEventDisableTiming) == cudaSuccess) &&
                  (cudaEventCreateWithFlags(&evJ, cudaEventDisableTiming) == cudaSuccess);
    }

    // KV cache copy on side stream (skips POS rows — written exclusively by k_hnr).
    // 4096 blocks * 1024 float4 = 4,194,304 = kvsz/4 exactly.
    if (side_ok) {
        cudaEventRecord(evF, 0);
        cudaStreamWaitEvent(s2, evF, 0);
        k_copy_kv_os<<<4096, 256, 0, s2>>>((const float4*)K_in, (const float4*)V_in,
                                           (float4*)outK, (float4*)outV);
        cudaEventRecord(evJ, s2);
    } else {
        k_copy_kv_ser<<<1184, 256>>>((const float4*)K_in, (const float4*)V_in,
                                     (float4*)outK, (float4*)outV, (int)(kvsz / 4));
    }

    // h = hidden_states ; hn = rms(h)*ln_in[0]
    k_rms_init<<<1, 512>>>(hs, ln_in, b_h, b_hn);

    for (int l = 0; l < NLAYER; l++) {
        const float* Wq_l = Wq + (size_t)l * 2048 * 2048;
        const float* Wk_l = Wk + (size_t)l * 512 * 2048;
        const float* Wv_l = Wv + (size_t)l * 512 * 2048;
        const float* Wo_l = Wo + (size_t)l * 2048 * 2048;
        const float* Wg_l = Wg + (size_t)l * 8192 * 2048;
        const float* Wu_l = Wu + (size_t)l * 8192 * 2048;
        const float* Wd_l = Wd + (size_t)l * 2048 * 8192;
        const float* Wplg_l = Wplg + (size_t)l * 256 * 2048;
        const float* Wplp_l = Wplp + (size_t)l * 2048 * 256;
        const float* K_l = K_in + (size_t)l * NKV * SEQ * HDIM;
        const float* V_l = V_in + (size_t)l * NKV * SEQ * HDIM;
        float* outK_l = outK + (size_t)l * NKV * SEQ * HDIM;
        float* outV_l = outV + (size_t)l * NKV * SEQ * HDIM;
        bool full = ((l + 1) % 5) == 0;
        const float* cp = full ? cos_f : cos_s;
        const float* sp = full ? sin_f : sin_s;
        const float* ln_in_next = ln_in + ((l + 1 < NLAYER) ? (l + 1) : 0) * DMODEL;

        // attention block
        k_qkv_cp<<<384, 256, SMEMB>>>(Wq_l, Wk_l, Wv_l, b_hn, b_qkv);
        k_hnr<<<12, 256>>>(b_qkv, qn + l * HDIM, kn + l * HDIM, cp, sp,
                           b_q, b_knew, b_vnew, outK_l, outV_l);
        k_scores<<<dim3(8, 33), 256>>>(b_q, K_l, b_knew, b_sc);
        k_softmax<<<8, 256>>>(b_sc, b_attn);
        k_attnv<<<dim3(8, 33), 256>>>(b_sc, V_l, b_vnew, b_attn);
        k_gemv_cp<<<256, 256, SMEMB>>>(Wo_l, b_attn, b_vec);
        k_rms_add_norm<<<1, 512>>>(b_vec, ln_pa + l * DMODEL, b_h,
                                   ln_pre + l * DMODEL, b_hn);
        // MLP block
        k_gateup_cp<<<2048, 256, SMEMB>>>(Wg_l, Wu_l, b_hn, b_act);
        k_wd_cp<<<1024, 256, SMEMB>>>(Wd_l, b_act, b_part);
        k_rms_add<4><<<1, 512>>>(b_part, ln_post + l * DMODEL, b_h);
        // per-layer block
        k_plg_rowblock<<<256, 256>>>(Wplg_l, b_h, pls + l * PLDIM, b_g2);
        k_gemv256<<<256, 256>>>(Wplp_l, b_g2, b_vec);
        k_rms_add_scale_norm<<<1, 512>>>(b_vec, ln_pl + l * DMODEL, lsc + l,
                                         b_h, ln_in_next, b_hn);
    }

    // join side stream, then final hidden state
    if (side_ok) cudaStreamWaitEvent(0, evJ, 0);
    k_copy<<<8, 256>>>(b_h, out, DMODEL);
}

// round 9
// speedup vs baseline: 1.0628x; 1.0278x over previous
#include <cuda_runtime.h>
#include <cstddef>
#include <cstdint>

#define NLAYER 8
#define DMODEL 2048
#define NHEAD 8
#define NKV 2
#define HDIM 256
#define SEQ 4096
#define FFDIM 8192
#define PLDIM 256
#define POS 2048
#define NS 2049          // valid attention positions (0..POS)
#define NCHUNK 33        // ceil(NS/64)
#define EPSF 1e-6f

// dynamic smem layout for cp.async GEMV kernels (in float4):
//   xs:  [0, 512)        x chunk (2048 floats)
//   ws:  [512, 512+3072) 3 stages x 8 warps x 128 float4
//   red: 8 floats after
#define XS4   512
#define WS4   3072
#define SS4   1024              // float4 per stage (8 warps * 128)
#define SMEMB ((XS4 + WS4) * 16 + 64)

// ---------------- scratch (device global, no allocation) ----------------
#define OFF_H     0
#define OFF_HN    2048
#define OFF_QKV   4096
#define OFF_Q     7168
#define OFF_KNEW  9216
#define OFF_VNEW  9728
#define OFF_ATTN  10240
#define OFF_ACT   12288
#define OFF_VEC   20480
#define OFF_G2    22528
#define OFF_APART 22784              // 8 heads * 33 chunks * 260 = 68640
#define OFF_WPART 91424              // Wd split-4 partials (4*2048)
__device__ __align__(16) float g_scratch[91424 + 8192];

// ---------------- helpers ----------------
__device__ __forceinline__ float warp_sum(float v) {
#pragma unroll
    for (int o = 16; o; o >>= 1) v += __shfl_xor_sync(0xffffffffu, v, o);
    return v;
}
__device__ __forceinline__ float warp_max(float v) {
#pragma unroll
    for (int o = 16; o; o >>= 1) v = fmaxf(v, __shfl_xor_sync(0xffffffffu, v, o));
    return v;
}
__device__ __forceinline__ float block_sum(float v) {
    __shared__ float red[16];
    __shared__ float tot;
    int t = threadIdx.x, nw = (int)(blockDim.x >> 5);
    __syncthreads();
    v = warp_sum(v);
    if ((t & 31) == 0) red[t >> 5] = v;
    __syncthreads();
    if (t < 32) {
        float s = (t < nw) ? red[t] : 0.f;
        s = warp_sum(s);
        if (t == 0) tot = s;
    }
    __syncthreads();
    return tot;
}
__device__ __forceinline__ float block_max(float v) {
    __shared__ float red[16];
    __shared__ float tot;
    int t = threadIdx.x, nw = (int)(blockDim.x >> 5);
    __syncthreads();
    v = warp_max(v);
    if ((t & 31) == 0) red[t >> 5] = v;
    __syncthreads();
    if (t < 32) {
        float s = (t < nw) ? red[t] : -3.0e38f;
        s = warp_max(s);
        if (t == 0) tot = s;
    }
    __syncthreads();
    return tot;
}
__device__ __forceinline__ float gelu_t(float x) {
    float x3 = x * x * x;
    return 0.5f * x * (1.f + tanhf(0.7978845608028654f * (x + 0.044715f * x3)));
}
__device__ __forceinline__ float dot4(float4 a, float4 b) {
    return a.x * b.x + a.y * b.y + a.z * b.z + a.w * b.w;
}
// PDL: trigger must follow a producer's last global write; wait precedes consumption.
__device__ __forceinline__ void pdl_trigger() {
    cudaTriggerProgrammaticLaunchCompletion();
}
__device__ __forceinline__ void pdl_wait() {
    cudaGridDependencySynchronize();
}

// ---------------- cp.async machinery ----------------
__device__ __forceinline__ void cp16(float4* sptr, const float4* gptr) {
    uint32_t sa = (uint32_t)__cvta_generic_to_shared(sptr);
    asm volatile("cp.async.cg.shared.global [%0], [%1], 16;\n" :: "r"(sa), "l"(gptr) : "memory");
}
__device__ __forceinline__ void cp_commit() {
    asm volatile("cp.async.commit_group;\n" ::: "memory");
}
__device__ __forceinline__ void rs_issue(const float4* gp, float4* wstage, int lane) {
#pragma unroll
    for (int i = 0; i < 4; i++) cp16(wstage + lane + 32 * i, gp + lane + 32 * i);
    cp_commit();
}
template <int NST>
__device__ __forceinline__ void rs_prologue(const float4* gp, float4* wswarp, int lane) {
#pragma unroll
    for (int s = 0; s < (NST < 3 ? NST : 3); s++)
        rs_issue(gp + s * 128, wswarp + s * SS4, lane);
}
template <int NST>
__device__ __forceinline__ float rs_loop(const float4* gp, float4* wswarp,
                                         const float4* xsw, int lane) {
    float acc = 0.f;
#pragma unroll
    for (int s = 0; s < NST; s++) {
        int rem = NST - 1 - s;
        if (rem >= 2)      asm volatile("cp.async.wait_group 2;\n" ::: "memory");
        else if (rem == 1) asm volatile("cp.async.wait_group 1;\n" ::: "memory");
        else               asm volatile("cp.async.wait_group 0;\n" ::: "memory");
        const float4* wstage = wswarp + (s % 3) * SS4;
#pragma unroll
        for (int i = 0; i < 4; i++)
            acc += dot4(wstage[lane + 32 * i], xsw[s * 128 + lane + 32 * i]);
        if (s + 3 < NST)
            rs_issue(gp + (s + 3) * 128, wswarp + ((s + 3) % 3) * SS4, lane);
    }
    return acc;
}

// ---------------- kernels ----------------

// side-stream KV copy: 4096 blocks * 1024 float4 = kvsz/4 exactly; skips POS rows.
__global__ void k_copy_kv_os(const float4* __restrict__ a, const float4* __restrict__ b,
                             float4* __restrict__ oa, float4* __restrict__ ob) {
    int base = blockIdx.x * 1024 + threadIdx.x;
#pragma unroll
    for (int k = 0; k < 4; k++) {
        int j = base + k * 256;
        float4 av = __ldcs(a + j);
        float4 bv = __ldcs(b + j);
        if (((j >> 6) & (SEQ - 1)) != POS) {
            oa[j] = av;
            ob[j] = bv;
        }
    }
}
__global__ void k_copy_kv_ser(const float4* __restrict__ a, const float4* __restrict__ b,
                              float4* __restrict__ oa, float4* __restrict__ ob, int n4) {
    int i = blockIdx.x * blockDim.x + threadIdx.x;
    int stride = gridDim.x * blockDim.x;
    for (; i < n4; i += stride) {
        float4 av = a[i], bv = b[i];
        if (((i >> 6) & (SEQ - 1)) != POS) { oa[i] = av; ob[i] = bv; }
    }
}

__global__ void k_copy(const float* __restrict__ src, float* __restrict__ dst, int n) {
    pdl_wait();
    int i = blockIdx.x * blockDim.x + threadIdx.x;
    if (i < n) dst[i] = src[i];
    pdl_trigger();
}

// h = hs ; hn = rms(hs)*w
__global__ void k_rms_init(const float* __restrict__ hs, const float* __restrict__ w,
                           float* __restrict__ h, float* __restrict__ hn) {
    int t = threadIdx.x;
    float v[4];
    float ss = 0.f;
#pragma unroll
    for (int i = 0; i < 4; i++) { v[i] = hs[t + 512 * i]; ss += v[i] * v[i]; }
    ss = block_sum(ss);
    float inv = rsqrtf(ss / (float)DMODEL + EPSF);
#pragma unroll
    for (int i = 0; i < 4; i++) {
        h[t + 512 * i] = v[i];
        hn[t + 512 * i] = v[i] * inv * w[t + 512 * i];
    }
    pdl_trigger();
}

// h += rms(sum partials)*w ; hn = rms(h_new)*w2
template <int NSPLIT>
__global__ void k_rms_add_norm_p(const float* __restrict__ part, const float* __restrict__ w1,
                                 float* __restrict__ h, const float* __restrict__ w2,
                                 float* __restrict__ hn) {
    pdl_wait();
    int t = threadIdx.x;
    float v[4], hv[4];
    float ss = 0.f;
#pragma unroll
    for (int i = 0; i < 4; i++) {
        int j = t + 512 * i;
        float r = 0.f;
#pragma unroll
        for (int s = 0; s < NSPLIT; s++) r += part[s * DMODEL + j];
        v[i] = r;
        ss += r * r;
    }
    ss = block_sum(ss);
    float inv = rsqrtf(ss / (float)DMODEL + EPSF);
    float ss2 = 0.f;
#pragma unroll
    for (int i = 0; i < 4; i++) {
        hv[i] = h[t + 512 * i] + v[i] * inv * w1[t + 512 * i];
        ss2 += hv[i] * hv[i];
    }
    ss2 = block_sum(ss2);
    float inv2 = rsqrtf(ss2 / (float)DMODEL + EPSF);
#pragma unroll
    for (int i = 0; i < 4; i++) {
        h[t + 512 * i] = hv[i];
        hn[t + 512 * i] = hv[i] * inv2 * w2[t + 512 * i];
    }
    pdl_trigger();
}

// h += rms(sum partials)*w   (no second norm)
template <int NSPLIT>
__global__ void k_rms_add(const float* __restrict__ part, const float* __restrict__ w,
                          float* __restrict__ h) {
    pdl_wait();
    int t = threadIdx.x;
    float v[4];
    float ss = 0.f;
#pragma unroll
    for (int i = 0; i < 4; i++) {
        int j = t + 512 * i;
        float r = 0.f;
#pragma unroll
        for (int s = 0; s < NSPLIT; s++) r += part[s * DMODEL + j];
        v[i] = r;
        ss += r * r;
    }
    ss = block_sum(ss);
    float inv = rsqrtf(ss / (float)DMODEL + EPSF);
#pragma unroll
    for (int i = 0; i < 4; i++) h[t + 512 * i] += v[i] * inv * w[t + 512 * i];
    pdl_trigger();
}

// h = (h + rms(raw)*w) * sc[0] ; hn = rms(h_new)*w2
__global__ void k_rms_add_scale_norm(const float* __restrict__ raw, const float* __restrict__ w,
                                     const float* __restrict__ sc, float* __restrict__ h,
                                     const float* __restrict__ w2, float* __restrict__ hn) {
    pdl_wait();
    int t = threadIdx.x;
    float v[4], hv[4];
    float ss = 0.f;
#pragma unroll
    for (int i = 0; i < 4; i++) { v[i] = raw[t + 512 * i]; ss += v[i] * v[i]; }
    ss = block_sum(ss);
    float inv = rsqrtf(ss / (float)DMODEL + EPSF);
    float s = sc[0];
    float ss2 = 0.f;
#pragma unroll
    for (int i = 0; i < 4; i++) {
        hv[i] = (h[t + 512 * i] + v[i] * inv * w[t + 512 * i]) * s;
        ss2 += hv[i] * hv[i];
    }
    ss2 = block_sum(ss2);
    float inv2 = rsqrtf(ss2 / (float)DMODEL + EPSF);
#pragma unroll
    for (int i = 0; i < 4; i++) {
        h[t + 512 * i] = hv[i];
        hn[t + 512 * i] = hv[i] * inv2 * w2[t + 512 * i];
    }
    pdl_trigger();
}

// fused q/k/v projection, cp.async + PDL (weight prologue overlaps predecessor)
__global__ void k_qkv_cp(const float* __restrict__ Wq, const float* __restrict__ Wk,
                         const float* __restrict__ Wv, const float* __restrict__ x,
                         float* __restrict__ y) {
    extern __shared__ float4 sm[];
    float4* xs = sm;
    float4* ws = sm + XS4;
    int t = threadIdx.x, warp = t >> 5, lane = t & 31;
    int row = blockIdx.x * 8 + warp;
    const float* W;
    int r;
    if (row < 2048) { W = Wq; r = row; }
    else if (row < 2560) { W = Wk; r = row - 2048; }
    else { W = Wv; r = row - 2560; }
    const float4* gp = (const float4*)(W + (size_t)r * DMODEL);
    float4* wswarp = ws + warp * 128;
    rs_prologue<4>(gp, wswarp, lane);          // independent of predecessor
    pdl_wait();                                 // hn now valid
    xs[t] = ((const float4*)x)[t];
    xs[t + 256] = ((const float4*)x)[t + 256];
    __syncthreads();
    float acc = rs_loop<4>(gp, wswarp, xs, lane);
    acc = warp_sum(acc);
    if (lane == 0) y[row] = acc;
    pdl_trigger();
}

// generic full-K (2048) GEMV + PDL (Wo: grid 256)
__global__ void k_gemv_cp(const float* __restrict__ W, const float* __restrict__ x,
                          float* __restrict__ y) {
    extern __shared__ float4 sm[];
    float4* xs = sm;
    float4* ws = sm + XS4;
    int t = threadIdx.x, warp = t >> 5, lane = t & 31;
    int row = blockIdx.x * 8 + warp;
    const float4* gp = (const float4*)(W + (size_t)row * DMODEL);
    float4* wswarp = ws + warp * 128;
    rs_prologue<4>(gp, wswarp, lane);
    pdl_wait();
    xs[t] = ((const float4*)x)[t];
    xs[t + 256] = ((const float4*)x)[t + 256];
    __syncthreads();
    float acc = rs_loop<4>(gp, wswarp, xs, lane);
    acc = warp_sum(acc);
    if (lane == 0) y[row] = acc;
    pdl_trigger();
}

// fused gate/up + PDL: grid 2048, block = 4 output rows (warps 0-3 Wg, 4-7 Wu)
__global__ void k_gateup_cp(const float* __restrict__ Wg, const float* __restrict__ Wu,
                            const float* __restrict__ x, float* __restrict__ act) {
    extern __shared__ float4 sm[];
    float4* xs = sm;
    float4* ws = sm + XS4;
    float* red = (float*)(sm + XS4 + WS4);
    int t = threadIdx.x, warp = t >> 5, lane = t & 31;
    int row = blockIdx.x * 4 + (warp & 3);
    const float* W = (warp < 4) ? Wg : Wu;
    const float4* gp = (const float4*)(W + (size_t)row * DMODEL);
    float4* wswarp = ws + warp * 128;
    rs_prologue<4>(gp, wswarp, lane);
    pdl_wait();
    xs[t] = ((const float4*)x)[t];
    xs[t + 256] = ((const float4*)x)[t + 256];
    __syncthreads();
    float acc = rs_loop<4>(gp, wswarp, xs, lane);
    acc = warp_sum(acc);
    if (lane == 0) red[warp] = acc;
    __syncthreads();
    if (t < 4) act[blockIdx.x * 4 + t] = gelu_t(red[t]) * red[t + 4];
    pdl_trigger();
}

// Wd split-4 + PDL: grid 1024 (grp 0..255 | chunk 0..3)
__global__ void k_wd_cp(const float* __restrict__ W, const float* __restrict__ x,
                        float* __restrict__ ypart) {
    extern __shared__ float4 sm[];
    float4* xs = sm;
    float4* ws = sm + XS4;
    int t = threadIdx.x, warp = t >> 5, lane = t & 31;
    int grp = blockIdx.x & 255;
    int c = blockIdx.x >> 8;
    int row = grp * 8 + warp;
    const float4* gp = (const float4*)(W + (size_t)row * FFDIM + c * 2048);
    float4* wswarp = ws + warp * 128;
    rs_prologue<4>(gp, wswarp, lane);
    pdl_wait();
    const float4* xp = (const float4*)(x + c * 2048);
    xs[t] = xp[t];
    xs[t + 256] = xp[t + 256];
    __syncthreads();
    float acc = rs_loop<4>(gp, wswarp, xs, lane);
    acc = warp_sum(acc);
    if (lane == 0) ypart[c * 2048 + row] = acc;
    pdl_trigger();
}

// per-layer gate + PDL: block per row (256), y[r] = gelu(W[r].h) * pl[r]
__global__ void k_plg_rowblock(const float* __restrict__ W, const float* __restrict__ x,
                               const float* __restrict__ pl, float* __restrict__ y) {
    int r = blockIdx.x, t = threadIdx.x;
    const float4* wr = (const float4*)(W + (size_t)r * DMODEL);
    float4 a0 = __ldcs(wr + t), a1 = __ldcs(wr + t + 256);   // weights first (independent)
    pdl_wait();
    const float4* xp = (const float4*)x;
    float s = dot4(a0, xp[t]) + dot4(a1, xp[t + 256]);
    s = block_sum(s);
    if (t == 0) y[r] = gelu_t(s) * pl[r];
    pdl_trigger();
}

// small gemv (plp, DIM=256) + PDL: warp per row, 8 rows/block
__global__ void k_gemv256(const float* __restrict__ W, const float* __restrict__ x,
                          float* __restrict__ y) {
    __shared__ float4 xs[64];
    int t = threadIdx.x;
    int warp = t >> 5, lane = t & 31;
    int row = blockIdx.x * 8 + warp;
    const float4* wr = (const float4*)(W + (size_t)row * 256);
    float4 a0 = __ldcs(wr + lane), a1 = __ldcs(wr + lane + 32);
    pdl_wait();
    if (t < 64) xs[t] = ((const float4*)x)[t];
    __syncthreads();
    float s = dot4(a0, xs[lane]) + dot4(a1, xs[lane + 32]);
    s = warp_sum(s);
    if (lane == 0) y[row] = s;
    pdl_trigger();
}

// per-head rms norm + (qn/kn) scale + rope + PDL
__global__ void k_hnr(const float* __restrict__ qkv, const float* __restrict__ qn,
                      const float* __restrict__ kn, const float* __restrict__ cosp,
                      const float* __restrict__ sinp, float* __restrict__ q,
                      float* __restrict__ knew, float* __restrict__ vnew,
                      float* __restrict__ outK_l, float* __restrict__ outV_l) {
    pdl_wait();
    int b = blockIdx.x, t = threadIdx.x;
    float x = qkv[b * 256 + t];
    float ss = block_sum(x * x);
    float inv = rsqrtf(ss / (float)HDIM + EPSF);
    __shared__ float sv[256];
    float val;
    if (b < 8) val = x * inv * qn[t];
    else if (b < 10) val = x * inv * kn[t];
    else val = x * inv;
    sv[t] = val;
    __syncthreads();
    float out;
    if (b < 10) {
        float other = (t < 128) ? -sv[t + 128] : sv[t - 128];
        out = val * cosp[t] + other * sinp[t];
    } else {
        out = val;
    }
    if (b < 8) {
        q[b * 256 + t] = out;
    } else if (b < 10) {
        int kv = b - 8;
        knew[kv * 256 + t] = out;
        outK_l[((size_t)kv * SEQ + POS) * HDIM + t] = out;
    } else {
        int kv = b - 10;
        vnew[kv * 256 + t] = out;
        outV_l[((size_t)kv * SEQ + POS) * HDIM + t] = out;
    }
    pdl_trigger();
}

// flash-style attention partials: grid (8 heads, 33 chunks of 64), 256 threads.
// per chunk: scores -> local max m, sum l, partial o[256]; write [o(256), m, l]
__global__ void k_attn_part(const float* __restrict__ q, const float* __restrict__ Kl,
                            const float* __restrict__ Vl, const float* __restrict__ knew,
                            const float* __restrict__ vnew, float* __restrict__ part) {
    int h = blockIdx.x, c = blockIdx.y, t = threadIdx.x;
    int kv = h >> 2;
    __shared__ float4 qs[64];
    __shared__ float sc[64];
    pdl_wait();
    if (t < 64) qs[t] = ((const float4*)(q + h * 256))[t];
    __syncthreads();
    int warp = t >> 5, lane = t & 31;
    const float* Kbase = Kl + (size_t)kv * SEQ * HDIM;
    const float* knv = knew + kv * HDIM;
    int s0 = c * 64;
#pragma unroll
    for (int i = 0; i < 8; i++) {
        int s = s0 + i * 8 + warp;
        float acc = -3.0e38f;
        if (s <= POS) {
            const float4* kr = (s == POS) ? (const float4*)knv
                                          : (const float4*)(Kbase + (size_t)s * HDIM);
            float4 a0 = __ldcs(kr + lane), a1 = __ldcs(kr + lane + 32);
            acc = dot4(a0, qs[lane]) + dot4(a1, qs[lane + 32]);
            acc = warp_sum(acc);
        }
        if (lane == 0) sc[i * 8 + warp] = acc;
    }
    __syncthreads();
    // local max + exp + sum over 64 entries
    float mv = (t < 64) ? sc[t] : -3.0e38f;
    float m = block_max(mv);
    float ev = 0.f;
    if (t < 64 && sc[t] > -1.0e38f) ev = __expf(sc[t] - m);
    float l = block_sum(ev);
    if (t < 64) sc[t] = ev;
    __syncthreads();
    // partial o[d] = sum_j e[j] * V[s0+j][d]
    const float* Vbase = Vl + (size_t)kv * SEQ * HDIM;
    const float* vnv = vnew + kv * HDIM;
    float o = 0.f;
#pragma unroll 4
    for (int j = 0; j < 64; j++) {
        int s = s0 + j;
        if (s > POS) break;
        const float* vr = (s == POS) ? vnv : (Vbase + (size_t)s * HDIM);
        o += sc[j] * __ldcs(vr + t);
    }
    float* pb = part + ((size_t)h * NCHUNK + c) * 260;
    pb[t] = o;
    if (t == 0) { pb[256] = m; pb[257] = l; }
    pdl_trigger();
}

// combine attention partials: grid 8 heads, 256 threads (= d)
__global__ void k_attn_comb(const float* __restrict__ part, float* __restrict__ attn) {
    int h = blockIdx.x, t = threadIdx.x;
    __shared__ float ml[NCHUNK], ll[NCHUNK];
    pdl_wait();
    const float* ph = part + (size_t)h * NCHUNK * 260;
    if (t < NCHUNK) {
        ml[t] = ph[t * 260 + 256];
        ll[t] = ph[t * 260 + 257];
    }
    __syncthreads();
    float M = -3.0e38f;
#pragma unroll
    for (int c = 0; c < NCHUNK; c++) M = fmaxf(M, ml[c]);
    float L = 0.f, o = 0.f;
#pragma unroll
    for (int c = 0; c < NCHUNK; c++) {
        float f = __expf(ml[c] - M);
        L += ll[c] * f;
        o += ph[c * 260 + t] * f;
    }
    attn[h * HDIM + t] = o / L;
    pdl_trigger();
}

// ---------------- host launcher ----------------
template <typename F, typename... Args>
static inline void pdl_launch(F fn, dim3 g, dim3 b, size_t smem, Args... args) {
    cudaLaunchConfig_t cfg = {};
    cfg.gridDim = g;
    cfg.blockDim = b;
    cfg.dynamicSmemBytes = smem;
    cfg.stream = 0;
    cudaLaunchAttribute at[1];
    at[0].id = cudaLaunchAttributeProgrammaticStreamSerialization;
    at[0].val.programmaticStreamSerializationAllowed = 1;
    cfg.attrs = at;
    cfg.numAttrs = 1;
    cudaLaunchKernelEx(&cfg, fn, args...);
}

extern "C" void kernel_launch(void* const* d_in, const int* in_sizes, int n_in,
                              void* d_out, int out_size) {
    const float* hs    = (const float*)d_in[0];
    const float* pls   = (const float*)d_in[3];
    const float* cos_s = (const float*)d_in[4];
    const float* sin_s = (const float*)d_in[5];
    const float* cos_f = (const float*)d_in[6];
    const float* sin_f = (const float*)d_in[7];
    const float* K_in  = (const float*)d_in[8];
    const float* V_in  = (const float*)d_in[9];
    const float* Wq    = (const float*)d_in[10];
    const float* Wk    = (const float*)d_in[11];
    const float* Wv    = (const float*)d_in[12];
    const float* Wo    = (const float*)d_in[13];
    const float* qn    = (const float*)d_in[14];
    const float* kn    = (const float*)d_in[15];
    const float* ln_in   = (const float*)d_in[16];
    const float* ln_pa   = (const float*)d_in[17];
    const float* ln_pre  = (const float*)d_in[18];
    const float* ln_post = (const float*)d_in[19];
    const float* ln_pl   = (const float*)d_in[20];
    const float* Wg    = (const float*)d_in[21];
    const float* Wu    = (const float*)d_in[22];
    const float* Wd    = (const float*)d_in[23];
    const float* Wplg  = (const float*)d_in[24];
    const float* Wplp  = (const float*)d_in[25];
    const float* lsc   = (const float*)d_in[26];

    float* out = (float*)d_out;
    const size_t kvsz = (size_t)NLAYER * NKV * SEQ * HDIM;  // 16,777,216 floats
    float* outK = out + DMODEL;
    float* outV = outK + kvsz;

    float* sb = nullptr;
    cudaGetSymbolAddress((void**)&sb, g_scratch);
    float* b_h     = sb + OFF_H;
    float* b_hn    = sb + OFF_HN;
    float* b_qkv   = sb + OFF_QKV;
    float* b_q     = sb + OFF_Q;
    float* b_knew  = sb + OFF_KNEW;
    float* b_vnew  = sb + OFF_VNEW;
    float* b_attn  = sb + OFF_ATTN;
    float* b_act   = sb + OFF_ACT;
    float* b_vec   = sb + OFF_VEC;
    float* b_g2    = sb + OFF_G2;
    float* b_apart = sb + OFF_APART;
    float* b_wpart = sb + OFF_WPART;

    // one-time setup: smem opt-in + side stream/events
    static bool attrs_done = false;
    if (!attrs_done) {
        cudaFuncSetAttribute(k_qkv_cp, cudaFuncAttributeMaxDynamicSharedMemorySize, SMEMB);
        cudaFuncSetAttribute(k_gemv_cp, cudaFuncAttributeMaxDynamicSharedMemorySize, SMEMB);
        cudaFuncSetAttribute(k_gateup_cp, cudaFuncAttributeMaxDynamicSharedMemorySize, SMEMB);
        cudaFuncSetAttribute(k_wd_cp, cudaFuncAttributeMaxDynamicSharedMemorySize, SMEMB);
        attrs_done = true;
    }
    static cudaStream_t s2 = nullptr;
    static cudaEvent_t evF = nullptr, evJ = nullptr;
    static bool side_ok = false;
    if (!s2) {
        int lo = 0, hi = 0;
        cudaDeviceGetStreamPriorityRange(&lo, &hi);
        side_ok = (cudaStreamCreateWithPriority(&s2, cudaStreamNonBlocking, lo) == cudaSuccess) &&
                  (cudaEventCreateWithFlags(&evF, cudaEventDisableTiming) == cudaSuccess) &&
                  (cudaEventCreateWithFlags(&evJ, cudaEventDisableTiming) == cudaSuccess);
    }

    // KV cache copy on side stream (skips POS rows — written exclusively by k_hnr).
    if (side_ok) {
        cudaEventRecord(evF, 0);
        cudaStreamWaitEvent(s2, evF, 0);
        k_copy_kv_os<<<4096, 256, 0, s2>>>((const float4*)K_in, (const float4*)V_in,
                                           (float4*)outK, (float4*)outV);
        cudaEventRecord(evJ, s2);
    } else {
        k_copy_kv_ser<<<1184, 256>>>((const float4*)K_in, (const float4*)V_in,
                                     (float4*)outK, (float4*)outV, (int)(kvsz / 4));
    }

    // h = hidden_states ; hn = rms(h)*ln_in[0]
    pdl_launch(k_rms_init, dim3(1), dim3(512), 0, hs, ln_in, b_h, b_hn);

    for (int l = 0; l < NLAYER; l++) {
        const float* Wq_l = Wq + (size_t)l * 2048 * 2048;
        const float* Wk_l = Wk + (size_t)l * 512 * 2048;
        const float* Wv_l = Wv + (size_t)l * 512 * 2048;
        const float* Wo_l = Wo + (size_t)l * 2048 * 2048;
        const float* Wg_l = Wg + (size_t)l * 8192 * 2048;
        const float* Wu_l = Wu + (size_t)l * 8192 * 2048;
        const float* Wd_l = Wd + (size_t)l * 2048 * 8192;
        const float* Wplg_l = Wplg + (size_t)l * 256 * 2048;
        const float* Wplp_l = Wplp + (size_t)l * 2048 * 256;
        const float* K_l = K_in + (size_t)l * NKV * SEQ * HDIM;
        const float* V_l = V_in + (size_t)l * NKV * SEQ * HDIM;
        float* outK_l = outK + (size_t)l * NKV * SEQ * HDIM;
        float* outV_l = outV + (size_t)l * NKV * SEQ * HDIM;
        bool full = ((l + 1) % 5) == 0;
        const float* cp = full ? cos_f : cos_s;
        const float* sp = full ? sin_f : sin_s;
        const float* ln_in_next = ln_in + ((l + 1 < NLAYER) ? (l + 1) : 0) * DMODEL;

        // attention block
        pdl_launch(k_qkv_cp, dim3(384), dim3(256), SMEMB, Wq_l, Wk_l, Wv_l,
                   (const float*)b_hn, b_qkv);
        pdl_launch(k_hnr, dim3(12), dim3(256), 0, (const float*)b_qkv,
                   qn + l * HDIM, kn + l * HDIM, cp, sp,
                   b_q, b_knew, b_vnew, outK_l, outV_l);
        pdl_launch(k_attn_part, dim3(8, NCHUNK), dim3(256), 0, (const float*)b_q,
                   K_l, V_l, (const float*)b_knew, (const float*)b_vnew, b_apart);
        pdl_launch(k_attn_comb, dim3(8), dim3(256), 0, (const float*)b_apart, b_attn);
        pdl_launch(k_gemv_cp, dim3(256), dim3(256), SMEMB, Wo_l,
                   (const float*)b_attn, b_vec);
        pdl_launch(k_rms_add_norm_p<1>, dim3(1), dim3(512), 0, (const float*)b_vec,
                   ln_pa + l * DMODEL, b_h, ln_pre + l * DMODEL, b_hn);
        // MLP block
        pdl_launch(k_gateup_cp, dim3(2048), dim3(256), SMEMB, Wg_l, Wu_l,
                   (const float*)b_hn, b_act);
        pdl_launch(k_wd_cp, dim3(1024), dim3(256), SMEMB, Wd_l,
                   (const float*)b_act, b_wpart);
        pdl_launch(k_rms_add<4>, dim3(1), dim3(512), 0, (const float*)b_wpart,
                   ln_post + l * DMODEL, b_h);
        // per-layer block
        pdl_launch(k_plg_rowblock, dim3(256), dim3(256), 0, Wplg_l,
                   (const float*)b_h, pls + l * PLDIM, b_g2);
        pdl_launch(k_gemv256, dim3(256), dim3(256), 0, Wplp_l,
                   (const float*)b_g2, b_vec);
        pdl_launch(k_rms_add_scale_norm, dim3(1), dim3(512), 0, (const float*)b_vec,
                   ln_pl + l * DMODEL, lsc + l, b_h, ln_in_next, b_hn);
    }

    // join side stream, then final hidden state
    if (side_ok) cudaStreamWaitEvent(0, evJ, 0);
    pdl_launch(k_copy, dim3(8), dim3(256), 0, (const float*)b_h, out, DMODEL);
}